// round 14
// baseline (speedup 1.0000x reference)
#include <cuda_runtime.h>
#include <cstdint>

// Problem dims (fixed by the reference)
#define T_STEPS 512
#define BATCH   256
#define DIN     128
#define DH      512
#define DOUT    128

// Persistent mega-kernel: 8 row-blocks x 16 col-blocks of 32x32 tiles
#define NCTA     128
#define THREADS  512

// SMEM strides (floats)
#define W_STRIDE   672    // 640 k + skew headroom; 672 % 32 == 0
#define H_STRIDE   544    // 512 k + skew headroom; 544 % 32 == 0
#define XS_STRIDE  160    // 128 k + skew headroom
#define RED_STRIDE 1056   // 1024 outputs + skew headroom
#define SMEM_FLOATS (32 * W_STRIDE + 32 * H_STRIDE + 32 * XS_STRIDE + 8 * RED_STRIDE)

typedef unsigned long long ull;

// -------------------- device scratch (no allocation allowed) --------------------
__device__ float    g_h[2][BATCH * DH];        // ping-pong hidden state (zero; restored per run)
__device__ unsigned g_flag[T_STEPS * NCTA];    // per-(step,tile) ready flags (restored per run)
__device__ unsigned g_arr, g_go, g_fin;        // self-resetting grid barrier

// -------------------- asm helpers --------------------
__device__ __forceinline__ ull fma2(ull a, ull b, ull c) {
    ull d;
    asm("fma.rn.f32x2 %0, %1, %2, %3;" : "=l"(d) : "l"(a), "l"(b), "l"(c));
    return d;
}
__device__ __forceinline__ float sum2(ull v) {
    float lo, hi;
    asm("mov.b64 {%0, %1}, %2;" : "=f"(lo), "=f"(hi) : "l"(v));
    return lo + hi;
}
__device__ __forceinline__ unsigned ld_acquire(const unsigned* p) {
    unsigned v;
    asm volatile("ld.acquire.gpu.global.u32 %0, [%1];" : "=r"(v) : "l"(p) : "memory");
    return v;
}
__device__ __forceinline__ void st_release(unsigned* p, unsigned v) {
    asm volatile("st.release.gpu.global.u32 [%0], %1;" :: "l"(p), "r"(v) : "memory");
}
__device__ __forceinline__ void poll1(const unsigned* f) {
    while (ld_acquire(f) == 0u) { }
}

// ==================== single fused persistent kernel ====================
// Phase 1: 512 recurrence steps; xproj fused as k 512..639 of the weight block.
//   512 threads: (rg,cg,kg) = rows 8rg..+7, cols 4cg..+3, kg = warp (16-way split-k,
//   8 k per 128-chunk per thread). Two-phase cross-kg reduction via 8-slice buffer.
// Phase 2: self-resetting grid barrier.
// Phase 3: out = h_final @ W2 + b2 + state restore for the next graph replay.
__global__ void __launch_bounds__(THREADS, 1)
rnn_kernel(const float* __restrict__ xs, const float* __restrict__ W1x,
           const float* __restrict__ W1h, const float* __restrict__ b1p,
           const float* __restrict__ W2, const float* __restrict__ b2p,
           float* __restrict__ out) {
    extern __shared__ float sm[];
    float* w_smT  = sm;                                       // [32 cols][672], k 0..639
    float* h_sm   = sm + 32 * W_STRIDE;                       // [32 rows][544]
    float* xs_sm  = sm + 32 * W_STRIDE + 32 * H_STRIDE;       // [32 rows][160]
    float* red    = xs_sm + 32 * XS_STRIDE;                   // [8][1056] two-phase buffer

    const int tid  = threadIdx.x;
    const int bid  = blockIdx.x;
    const int cb   = bid & 15;
    const int rb   = bid >> 4;
    const int col0 = cb * 32;
    const int row0 = rb * 32;

    const int l  = tid & 31;          // lane
    const int rg = tid & 3;           // row-group: rows 8rg..8rg+7
    const int cg = (tid >> 2) & 7;    // col-group: cols 4cg..4cg+3
    const int kg = tid >> 5;          // warp id == k-group (0..15): k-slice kg*8 per chunk

    // Staging role: warp kg covers rows 2kg, 2kg+1; lane = 16B seg.
    const int sr = 2 * kg + (l >> 4); // staging row 0..31
    const int ss = l & 15;            // float4 seg (and ss+16)

    // ---- Prologue: stage W1h^T (k 0..511). Element (c,k) -> c*672 + 4*(c>>2) + k.
#pragma unroll
    for (int i = 0; i < 8; i++) {
        int idx = i * THREADS + tid;                          // 0..4095
        int c4  = idx & 7;
        int k   = idx >> 3;
        float4 v = *reinterpret_cast<const float4*>(W1h + (size_t)k * DH + col0 + c4 * 4);
        float* bp = w_smT + 4 * c4 + k;                       // skew = 4*c4 for all 4 elems
        bp[(4 * c4 + 0) * W_STRIDE] = v.x;
        bp[(4 * c4 + 1) * W_STRIDE] = v.y;
        bp[(4 * c4 + 2) * W_STRIDE] = v.z;
        bp[(4 * c4 + 3) * W_STRIDE] = v.w;
    }
    // ---- Prologue: stage W1x^T (k 512..639)
#pragma unroll
    for (int i = 0; i < 2; i++) {
        int idx = i * THREADS + tid;                          // 0..1023
        int c4  = idx & 7;
        int k   = idx >> 3;                                   // 0..127
        float4 v = *reinterpret_cast<const float4*>(W1x + (size_t)k * DH + col0 + c4 * 4);
        float* bp = w_smT + 4 * c4 + 512 + k;
        bp[(4 * c4 + 0) * W_STRIDE] = v.x;
        bp[(4 * c4 + 1) * W_STRIDE] = v.y;
        bp[(4 * c4 + 2) * W_STRIDE] = v.z;
        bp[(4 * c4 + 3) * W_STRIDE] = v.w;
    }
    // ---- Prologue: stage xs[0]
    {
        const float* src = xs + (size_t)(row0 + sr) * DIN + ss * 4;
        float4 a = __ldg(reinterpret_cast<const float4*>(src));
        float4 b = __ldg(reinterpret_cast<const float4*>(src + 64));
        float* dst = xs_sm + (size_t)sr * XS_STRIDE + 4 * (sr >> 3) + ss * 4;
        *reinterpret_cast<float4*>(dst)      = a;
        *reinterpret_cast<float4*>(dst + 64) = b;
    }
    const float bias = b1p[0];
    __syncthreads();

    // GEMM base pointers (skews folded in)
    const float* wc0 = w_smT + (size_t)(4 * cg + 0) * W_STRIDE + 4 * cg;
    const float* wc1 = wc0 + W_STRIDE;
    const float* wc2 = wc1 + W_STRIDE;
    const float* wc3 = wc2 + W_STRIDE;
    const float* hb  = h_sm  + (size_t)(8 * rg) * H_STRIDE  + 4 * rg;
    const float* xb  = xs_sm + (size_t)(8 * rg) * XS_STRIDE + 4 * rg;

    const float* hin  = g_h[0];
    float*       hout = g_h[1];
    const int    base = cb >> 2;                // rotated chunk start (spread L2 load)
    const int    ko   = kg * 8;                 // this warp's k-offset within each chunk

    // =================== Phase 1: recurrence ===================
    for (int s = 0; s < T_STEPS; s++) {
        ull acc[8][4];
#pragma unroll
        for (int j = 0; j < 8; j++)
#pragma unroll
            for (int i = 0; i < 4; i++) acc[j][i] = 0ull;

        // One 4-k GEMM block: 8 rows x 4 cols, packed f32x2.
        auto gemm4 = [&](const float* hrow, int hstride, int hk, int wk) {
            ulonglong2 wv0 = *reinterpret_cast<const ulonglong2*>(wc0 + wk);
            ulonglong2 wv1 = *reinterpret_cast<const ulonglong2*>(wc1 + wk);
            ulonglong2 wv2 = *reinterpret_cast<const ulonglong2*>(wc2 + wk);
            ulonglong2 wv3 = *reinterpret_cast<const ulonglong2*>(wc3 + wk);
#pragma unroll
            for (int j = 0; j < 8; j++) {
                ulonglong2 hv = *reinterpret_cast<const ulonglong2*>(
                    hrow + (size_t)j * hstride + hk);
                acc[j][0] = fma2(hv.x, wv0.x, acc[j][0]);
                acc[j][0] = fma2(hv.y, wv0.y, acc[j][0]);
                acc[j][1] = fma2(hv.x, wv1.x, acc[j][1]);
                acc[j][1] = fma2(hv.y, wv1.y, acc[j][1]);
                acc[j][2] = fma2(hv.x, wv2.x, acc[j][2]);
                acc[j][2] = fma2(hv.y, wv2.y, acc[j][2]);
                acc[j][3] = fma2(hv.x, wv3.x, acc[j][3]);
                acc[j][3] = fma2(hv.y, wv3.y, acc[j][3]);
            }
        };

        const unsigned* fl = &g_flag[(size_t)(s - 1) * NCTA + rb * 16];
        const int tile_a = (ss >> 3);           // producer tiles this thread's restage reads
        float4 t0, t1;

        // ---- xs half 1; acquire chunk c0's producers; LDG c0 under xs half 2 ----
        const int c0 = base;
        gemm4(xb, XS_STRIDE, ko, 512 + ko);
        if (s > 0) {
            poll1(fl + c0 * 4 + tile_a);
            poll1(fl + c0 * 4 + tile_a + 2);
        }
        {
            const float* src = hin + (size_t)(row0 + sr) * DH + c0 * 128 + ss * 4;
            t0 = __ldcg(reinterpret_cast<const float4*>(src));
            t1 = __ldcg(reinterpret_cast<const float4*>(src + 64));
        }
        gemm4(xb, XS_STRIDE, ko + 4, 516 + ko);
        {
            float* dst = h_sm + (size_t)sr * H_STRIDE + 4 * (sr >> 3) + c0 * 128 + ss * 4;
            *reinterpret_cast<float4*>(dst)      = t0;
            *reinterpret_cast<float4*>(dst + 64) = t1;
        }
        __syncthreads();

        // ---- h chunks, software-pipelined ----
#pragma unroll
        for (int j3 = 0; j3 < 3; j3++) {
            const int cj = (base + j3) & 3;
            const int cn = (base + j3 + 1) & 3;
            gemm4(hb, H_STRIDE, cj * 128 + ko, cj * 128 + ko);
            if (s > 0) {
                poll1(fl + cn * 4 + tile_a);
                poll1(fl + cn * 4 + tile_a + 2);
            }
            {
                const float* src = hin + (size_t)(row0 + sr) * DH + cn * 128 + ss * 4;
                t0 = __ldcg(reinterpret_cast<const float4*>(src));
                t1 = __ldcg(reinterpret_cast<const float4*>(src + 64));
            }
            gemm4(hb, H_STRIDE, cj * 128 + ko + 4, cj * 128 + ko + 4);
            {
                float* dst = h_sm + (size_t)sr * H_STRIDE + 4 * (sr >> 3) + cn * 128 + ss * 4;
                *reinterpret_cast<float4*>(dst)      = t0;
                *reinterpret_cast<float4*>(dst + 64) = t1;
            }
            __syncthreads();
        }

        // ---- last chunk; xs[s+1] LDG hidden under its second half ----
        {
            const int c3 = (base + 3) & 3;
            gemm4(hb, H_STRIDE, c3 * 128 + ko, c3 * 128 + ko);
            if (s < T_STEPS - 1) {
                const float* src = xs + ((size_t)(s + 1) * BATCH + row0 + sr) * DIN + ss * 4;
                t0 = __ldg(reinterpret_cast<const float4*>(src));
                t1 = __ldg(reinterpret_cast<const float4*>(src + 64));
            }
            gemm4(hb, H_STRIDE, c3 * 128 + ko + 4, c3 * 128 + ko + 4);
            if (s < T_STEPS - 1) {
                // Safe: all warps passed the c0 barrier => xs gemm for step s is done.
                float* dst = xs_sm + (size_t)sr * XS_STRIDE + 4 * (sr >> 3) + ss * 4;
                *reinterpret_cast<float4*>(dst)      = t0;
                *reinterpret_cast<float4*>(dst + 64) = t1;
            }
        }

        // ---- two-phase cross-kg reduction (8-slice buffer) ----
        const int orow = tid >> 4;
        const int ocol = 2 * (tid & 15);
        const float* rsrc = red + (size_t)orow * 32 + 8 * (orow >> 3) + ocol;
        float2 racc = make_float2(0.f, 0.f);

        // Phase A: kg 0..7 write
        if (kg < 8) {
            float* rbse = red + (size_t)kg * RED_STRIDE + 8 * rg + 4 * cg;
#pragma unroll
            for (int j = 0; j < 8; j++) {
                float4 pv;
                pv.x = sum2(acc[j][0]); pv.y = sum2(acc[j][1]);
                pv.z = sum2(acc[j][2]); pv.w = sum2(acc[j][3]);
                *reinterpret_cast<float4*>(rbse + (size_t)(8 * rg + j) * 32) = pv;
            }
        }
        __syncthreads();
#pragma unroll
        for (int g = 0; g < 8; g++) {
            float2 b = *reinterpret_cast<const float2*>(rsrc + (size_t)g * RED_STRIDE);
            racc.x += b.x; racc.y += b.y;
        }
        __syncthreads();
        // Phase B: kg 8..15 write into the same slots
        if (kg >= 8) {
            float* rbse = red + (size_t)(kg - 8) * RED_STRIDE + 8 * rg + 4 * cg;
#pragma unroll
            for (int j = 0; j < 8; j++) {
                float4 pv;
                pv.x = sum2(acc[j][0]); pv.y = sum2(acc[j][1]);
                pv.z = sum2(acc[j][2]); pv.w = sum2(acc[j][3]);
                *reinterpret_cast<float4*>(rbse + (size_t)(8 * rg + j) * 32) = pv;
            }
        }
        __syncthreads();
#pragma unroll
        for (int g = 0; g < 8; g++) {
            float2 b = *reinterpret_cast<const float2*>(rsrc + (size_t)g * RED_STRIDE);
            racc.x += b.x; racc.y += b.y;
        }
        {
            float2 o;
            o.x = tanhf(racc.x + bias);
            o.y = tanhf(racc.y + bias);
            *reinterpret_cast<float2*>(
                hout + (size_t)(row0 + orow) * DH + col0 + ocol) = o;
        }
        __syncthreads();                                      // hout STGs + xs STS ordered
        if (s < T_STEPS - 1 && tid == 0)
            st_release(&g_flag[(size_t)s * NCTA + bid], 1u);

        const float* tmp = hin; hin = hout; hout = const_cast<float*>(tmp);
    }
    // 512 steps (even): final h lives in g_h[0].

    // =================== Phase 2: grid barrier (self-resetting) ===================
    __threadfence();
    __syncthreads();
    if (tid == 0) {
        unsigned my = atomicAdd(&g_arr, 1u);
        if (my == NCTA - 1) {
            g_arr = 0u;
            st_release(&g_go, 1u);
        } else {
            while (ld_acquire(&g_go) == 0u) { }
        }
        unsigned f2 = atomicAdd(&g_fin, 1u);
        if (f2 == NCTA - 1) {                                 // provably last past the poll
            g_fin = 0u;
            st_release(&g_go, 0u);
        }
    }
    __syncthreads();

    // =================== Phase 3: out = h_final @ W2 + b2, + state restore ===================
    const int r0 = 2 * bid;                                   // 2 batch rows per CTA
    {
        int r = tid >> 8, c2 = tid & 255;                     // 512 x float2 = 1024 floats
        float2 v = __ldcg(reinterpret_cast<const float2*>(
            &g_h[0][(size_t)(r0 + r) * DH + c2 * 2]));
        *reinterpret_cast<float2*>(&h_sm[r * DH + c2 * 2]) = v;
    }
    __syncthreads();

    // Restore state for next replay: zero our flag slice + our 2 h rows.
    g_flag[(size_t)bid * 512 + tid] = 0u;
    *reinterpret_cast<float2*>(&g_h[0][(size_t)r0 * DH + tid * 2]) = make_float2(0.f, 0.f);

    if (tid < 256) {
        const float b2v = b2p[0];
        const int   orw = tid >> 7;                           // 0..1
        const int   o   = tid & 127;
        const float* hsr = h_sm + orw * DH;
        float acc = b2v;
#pragma unroll 8
        for (int k = 0; k < DH; k++)
            acc += hsr[k] * __ldg(W2 + (size_t)k * DOUT + o);
        out[(size_t)(r0 + orw) * DOUT + o] = acc;
    }
}

// -------------------- launch --------------------
extern "C" void kernel_launch(void* const* d_in, const int* in_sizes, int n_in,
                              void* d_out, int out_size) {
    const float* xs  = (const float*)d_in[0];
    const float* W1x = (const float*)d_in[1];
    const float* W1h = (const float*)d_in[2];
    const float* b1  = (const float*)d_in[3];
    const float* W2  = (const float*)d_in[4];
    const float* b2  = (const float*)d_in[5];
    float* out = (float*)d_out;

    (void)in_sizes; (void)n_in; (void)out_size;

    cudaFuncSetAttribute(rnn_kernel, cudaFuncAttributeMaxDynamicSharedMemorySize,
                         SMEM_FLOATS * (int)sizeof(float));

    rnn_kernel<<<NCTA, THREADS, SMEM_FLOATS * sizeof(float)>>>(
        xs, W1x, W1h, b1, W2, b2, out);
}

// round 16
// speedup vs baseline: 1.1284x; 1.1284x over previous
#include <cuda_runtime.h>
#include <cstdint>

// Problem dims (fixed by the reference)
#define T_STEPS 512
#define BATCH   256
#define DIN     128
#define DH      512
#define DOUT    128

// Persistent mega-kernel: 8 row-blocks x 16 col-blocks of 32x32 tiles
#define NCTA     128
#define THREADS  256

// SMEM strides (floats)
#define W_STRIDE   672    // 640 k + skew headroom; 672 % 32 == 0
#define H_STRIDE   544    // 512 k + skew headroom; 544 % 32 == 0
#define XS_STRIDE  160    // 128 k + skew headroom
#define RED_STRIDE 1056   // 1024 outputs + skew headroom
#define SMEM_FLOATS (32 * W_STRIDE + 32 * H_STRIDE + 32 * XS_STRIDE + 8 * RED_STRIDE)

typedef unsigned long long ull;

// -------------------- device scratch (no allocation allowed) --------------------
__device__ float    g_h[2][BATCH * DH];        // ping-pong hidden state (zero; restored per run)
__device__ unsigned g_flag[T_STEPS * NCTA];    // per-(step,tile) ready flags (restored per run)
__device__ unsigned g_arr, g_go, g_fin;        // self-resetting grid barrier

// -------------------- asm helpers --------------------
__device__ __forceinline__ ull fma2(ull a, ull b, ull c) {
    ull d;
    asm("fma.rn.f32x2 %0, %1, %2, %3;" : "=l"(d) : "l"(a), "l"(b), "l"(c));
    return d;
}
__device__ __forceinline__ float sum2(ull v) {
    float lo, hi;
    asm("mov.b64 {%0, %1}, %2;" : "=f"(lo), "=f"(hi) : "l"(v));
    return lo + hi;
}
__device__ __forceinline__ unsigned ld_acquire(const unsigned* p) {
    unsigned v;
    asm volatile("ld.acquire.gpu.global.u32 %0, [%1];" : "=r"(v) : "l"(p) : "memory");
    return v;
}
__device__ __forceinline__ void st_release(unsigned* p, unsigned v) {
    asm volatile("st.release.gpu.global.u32 [%0], %1;" :: "l"(p), "r"(v) : "memory");
}
__device__ __forceinline__ void poll1(const unsigned* f) {
    while (ld_acquire(f) == 0u) { }
}

// ==================== single fused persistent kernel ====================
// Phase 1: 512 recurrence steps; xproj fused as k 512..639 of the weight block.
//   256 threads: (rg,cg,kg) = rows 8rg..+7, cols 4cg..+3, kg = warp (8-way split-k,
//   16 k per 128-chunk per warp). Shared staged h; per-lane flag acquires.
//   R16 delta vs R13: each loop chunk's poll+LDG issued BEFORE the previous
//   chunk's full 16-k GEMM (full-latency coverage); numerics bit-exact.
// Phase 2: self-resetting grid barrier.
// Phase 3: out = h_final @ W2 + b2 + state restore for the next graph replay.
__global__ void __launch_bounds__(THREADS, 1)
rnn_kernel(const float* __restrict__ xs, const float* __restrict__ W1x,
           const float* __restrict__ W1h, const float* __restrict__ b1p,
           const float* __restrict__ W2, const float* __restrict__ b2p,
           float* __restrict__ out) {
    extern __shared__ float sm[];
    float* w_smT  = sm;                                       // [32 cols][672], k 0..639
    float* h_sm   = sm + 32 * W_STRIDE;                       // [32 rows][544]
    float* xs_sm  = sm + 32 * W_STRIDE + 32 * H_STRIDE;       // [32 rows][160]
    float* red    = xs_sm + 32 * XS_STRIDE;                   // [8][1056] reduction buffer

    const int tid  = threadIdx.x;
    const int bid  = blockIdx.x;
    const int cb   = bid & 15;
    const int rb   = bid >> 4;
    const int col0 = cb * 32;
    const int row0 = rb * 32;

    const int w  = tid >> 5;          // warp (staging role)
    const int l  = tid & 31;          // lane
    const int rg = tid & 3;           // GEMM row-group: rows 8rg..8rg+7
    const int cg = (tid >> 2) & 7;    // GEMM col-group: cols 4cg..4cg+3
    const int kg = w;                 // k-group: k offset kg*16 within each 128-chunk

    // ---- Prologue: stage W1h^T (k 0..511). Element (c,k) -> c*672 + 4*(c>>2) + k.
#pragma unroll
    for (int i = 0; i < 16; i++) {
        int idx = i * THREADS + tid;                          // 0..4095
        int c4  = idx & 7;
        int k   = idx >> 3;
        float4 v = *reinterpret_cast<const float4*>(W1h + (size_t)k * DH + col0 + c4 * 4);
        float* bp = w_smT + 4 * c4 + k;                       // skew = 4*c4 for all 4 elems
        bp[(4 * c4 + 0) * W_STRIDE] = v.x;
        bp[(4 * c4 + 1) * W_STRIDE] = v.y;
        bp[(4 * c4 + 2) * W_STRIDE] = v.z;
        bp[(4 * c4 + 3) * W_STRIDE] = v.w;
    }
    // ---- Prologue: stage W1x^T (k 512..639)
#pragma unroll
    for (int i = 0; i < 4; i++) {
        int idx = i * THREADS + tid;                          // 0..1023
        int c4  = idx & 7;
        int k   = idx >> 3;                                   // 0..127
        float4 v = *reinterpret_cast<const float4*>(W1x + (size_t)k * DH + col0 + c4 * 4);
        float* bp = w_smT + 4 * c4 + 512 + k;
        bp[(4 * c4 + 0) * W_STRIDE] = v.x;
        bp[(4 * c4 + 1) * W_STRIDE] = v.y;
        bp[(4 * c4 + 2) * W_STRIDE] = v.z;
        bp[(4 * c4 + 3) * W_STRIDE] = v.w;
    }
    // ---- Prologue: stage xs[0]
#pragma unroll
    for (int j = 0; j < 4; j++) {
        int r = 4 * w + j;
        float4 v = __ldg(reinterpret_cast<const float4*>(
            xs + (size_t)(row0 + r) * DIN + 4 * l));
        *reinterpret_cast<float4*>(
            xs_sm + (size_t)r * XS_STRIDE + 4 * (r >> 3) + 4 * l) = v;
    }
    const float bias = b1p[0];
    __syncthreads();

    // GEMM base pointers (skews folded in)
    const float* wc0 = w_smT + (size_t)(4 * cg + 0) * W_STRIDE + 4 * cg;
    const float* wc1 = wc0 + W_STRIDE;
    const float* wc2 = wc1 + W_STRIDE;
    const float* wc3 = wc2 + W_STRIDE;
    const float* hb  = h_sm  + (size_t)(8 * rg) * H_STRIDE  + 4 * rg;
    const float* xb  = xs_sm + (size_t)(8 * rg) * XS_STRIDE + 4 * rg;

    const float* hin  = g_h[0];
    float*       hout = g_h[1];
    const int    base = cb >> 2;                // rotated chunk start (spread L2 load)

    // =================== Phase 1: recurrence ===================
    for (int s = 0; s < T_STEPS; s++) {
        ull acc[8][4];
#pragma unroll
        for (int j = 0; j < 8; j++)
#pragma unroll
            for (int i = 0; i < 4; i++) acc[j][i] = 0ull;

        // 8-k GEMM slice: 8 rows x 4 cols, packed f32x2.
        auto gemm8 = [&](const float* hrow, int hstride, int hk, int wk) {
#pragma unroll
            for (int kk = 0; kk < 8; kk += 4) {
                ulonglong2 wv0 = *reinterpret_cast<const ulonglong2*>(wc0 + wk + kk);
                ulonglong2 wv1 = *reinterpret_cast<const ulonglong2*>(wc1 + wk + kk);
                ulonglong2 wv2 = *reinterpret_cast<const ulonglong2*>(wc2 + wk + kk);
                ulonglong2 wv3 = *reinterpret_cast<const ulonglong2*>(wc3 + wk + kk);
#pragma unroll
                for (int j = 0; j < 8; j++) {
                    ulonglong2 hv = *reinterpret_cast<const ulonglong2*>(
                        hrow + (size_t)j * hstride + hk + kk);
                    acc[j][0] = fma2(hv.x, wv0.x, acc[j][0]);
                    acc[j][0] = fma2(hv.y, wv0.y, acc[j][0]);
                    acc[j][1] = fma2(hv.x, wv1.x, acc[j][1]);
                    acc[j][1] = fma2(hv.y, wv1.y, acc[j][1]);
                    acc[j][2] = fma2(hv.x, wv2.x, acc[j][2]);
                    acc[j][2] = fma2(hv.y, wv2.y, acc[j][2]);
                    acc[j][3] = fma2(hv.x, wv3.x, acc[j][3]);
                    acc[j][3] = fma2(hv.y, wv3.y, acc[j][3]);
                }
            }
        };

        // Per-lane flag base: lane l's restage column 4l lies in tile (l>>3) of each chunk.
        const unsigned* fl = &g_flag[(size_t)(s - 1) * NCTA + rb * 16 + (l >> 3)];
        const int ko = kg * 16;
        float4 t[4];

        // ---- xs half 1; acquire chunk c0's producer; LDG c0 under xs half 2 ----
        const int c0 = base;
        gemm8(xb, XS_STRIDE, ko, 512 + ko);
        if (s > 0) poll1(fl + c0 * 4);                        // acquire orders LDGs below
        {
            const float* src = hin + (size_t)(row0 + 4 * w) * DH + c0 * 128 + 4 * l;
#pragma unroll
            for (int j = 0; j < 4; j++)
                t[j] = __ldcg(reinterpret_cast<const float4*>(src + (size_t)j * DH));
        }
        gemm8(xb, XS_STRIDE, ko + 8, 520 + ko);
        {
#pragma unroll
            for (int j = 0; j < 4; j++) {
                int r = 4 * w + j;
                *reinterpret_cast<float4*>(
                    h_sm + (size_t)r * H_STRIDE + 4 * (r >> 3) + c0 * 128 + 4 * l) = t[j];
            }
        }
        __syncthreads();

        // ---- h chunks: poll+LDG of cn issued BEFORE cj's full 16-k GEMM ----
#pragma unroll
        for (int j3 = 0; j3 < 3; j3++) {
            const int cj = (base + j3) & 3;
            const int cn = (base + j3 + 1) & 3;
            if (s > 0) poll1(fl + cn * 4);                    // cn producers are a full step old
            {
                const float* src = hin + (size_t)(row0 + 4 * w) * DH + cn * 128 + 4 * l;
#pragma unroll
                for (int j = 0; j < 4; j++)
                    t[j] = __ldcg(reinterpret_cast<const float4*>(src + (size_t)j * DH));
            }
            gemm8(hb, H_STRIDE, cj * 128 + ko, cj * 128 + ko);        // 512+ cyc of cover
            gemm8(hb, H_STRIDE, cj * 128 + ko + 8, cj * 128 + ko + 8);
            {
#pragma unroll
                for (int j = 0; j < 4; j++) {
                    int r = 4 * w + j;
                    *reinterpret_cast<float4*>(
                        h_sm + (size_t)r * H_STRIDE + 4 * (r >> 3) + cn * 128 + 4 * l) = t[j];
                }
            }
            __syncthreads();
        }

        // ---- last chunk; xs[s+1] LDG hidden under its second half ----
        {
            const int c3 = (base + 3) & 3;
            gemm8(hb, H_STRIDE, c3 * 128 + ko, c3 * 128 + ko);
            if (s < T_STEPS - 1) {
                const float* src = xs + ((size_t)(s + 1) * BATCH + row0 + 4 * w) * DIN + 4 * l;
#pragma unroll
                for (int j = 0; j < 4; j++)
                    t[j] = __ldg(reinterpret_cast<const float4*>(src + (size_t)j * DIN));
            }
            gemm8(hb, H_STRIDE, c3 * 128 + ko + 8, c3 * 128 + ko + 8);
            if (s < T_STEPS - 1) {
                // Safe: all warps' xs GEMM for step s finished before the c0 barrier.
#pragma unroll
                for (int j = 0; j < 4; j++) {
                    int r = 4 * w + j;
                    *reinterpret_cast<float4*>(
                        xs_sm + (size_t)r * XS_STRIDE + 4 * (r >> 3) + 4 * l) = t[j];
                }
            }
        }

        // ---- cross-kg reduction (skewed, conflict-free) ----
        {
            float* rbse = red + (size_t)kg * RED_STRIDE + 8 * rg + 4 * cg;
#pragma unroll
            for (int j = 0; j < 8; j++) {
                float4 pv;
                pv.x = sum2(acc[j][0]); pv.y = sum2(acc[j][1]);
                pv.z = sum2(acc[j][2]); pv.w = sum2(acc[j][3]);
                *reinterpret_cast<float4*>(rbse + (size_t)(8 * rg + j) * 32) = pv;
            }
        }
        __syncthreads();
        {
            const int orow = tid >> 3;
            const int ocol = 4 * (tid & 7);
            const float* rsrc = red + (size_t)orow * 32 + 8 * (orow >> 3) + ocol;
            float4 a = *reinterpret_cast<const float4*>(rsrc);
#pragma unroll
            for (int g = 1; g < 8; g++) {
                float4 b = *reinterpret_cast<const float4*>(rsrc + (size_t)g * RED_STRIDE);
                a.x += b.x; a.y += b.y; a.z += b.z; a.w += b.w;
            }
            float4 o;
            o.x = tanhf(a.x + bias); o.y = tanhf(a.y + bias);
            o.z = tanhf(a.z + bias); o.w = tanhf(a.w + bias);
            *reinterpret_cast<float4*>(
                hout + (size_t)(row0 + orow) * DH + col0 + ocol) = o;
        }
        __syncthreads();                                      // hout STGs + xs STS ordered
        if (s < T_STEPS - 1 && tid == 0)
            st_release(&g_flag[(size_t)s * NCTA + bid], 1u);

        const float* tmp = hin; hin = hout; hout = const_cast<float*>(tmp);
    }
    // 512 steps (even): final h lives in g_h[0].

    // =================== Phase 2: grid barrier (self-resetting) ===================
    __threadfence();
    __syncthreads();
    if (tid == 0) {
        unsigned my = atomicAdd(&g_arr, 1u);
        if (my == NCTA - 1) {
            g_arr = 0u;
            st_release(&g_go, 1u);
        } else {
            while (ld_acquire(&g_go) == 0u) { }
        }
        unsigned f2 = atomicAdd(&g_fin, 1u);
        if (f2 == NCTA - 1) {                                 // provably last past the poll
            g_fin = 0u;
            st_release(&g_go, 0u);
        }
    }
    __syncthreads();

    // =================== Phase 3: out = h_final @ W2 + b2, + state restore ===================
    float* hsm = sm;                                          // reuse SMEM
    const int r0 = 2 * bid;                                   // 2 batch rows per CTA
    {
        int r = tid >> 7, c4 = tid & 127;                     // 256 float4 = 2 rows
        float4 v = __ldcg(reinterpret_cast<const float4*>(
            &g_h[0][(size_t)(r0 + r) * DH + c4 * 4]));
        *reinterpret_cast<float4*>(&hsm[r * DH + c4 * 4]) = v;
    }
    __syncthreads();

    // Restore state for next replay: zero our flag slice + our 2 h rows.
    {
        uint2 z2 = make_uint2(0u, 0u);
        *reinterpret_cast<uint2*>(&g_flag[(size_t)bid * 512 + tid * 2]) = z2;
        int r = tid >> 7, c4 = tid & 127;
        *reinterpret_cast<float4*>(&g_h[0][(size_t)(r0 + r) * DH + c4 * 4]) =
            make_float4(0.f, 0.f, 0.f, 0.f);
    }

    const float b2v = b2p[0];
    const int   orw = tid >> 7;                               // 0..1
    const int   o   = tid & 127;
    const float* hsr = hsm + orw * DH;
    float acc = b2v;
#pragma unroll 8
    for (int k = 0; k < DH; k++)
        acc += hsr[k] * __ldg(W2 + (size_t)k * DOUT + o);
    out[(size_t)(r0 + orw) * DOUT + o] = acc;
}

// -------------------- launch --------------------
extern "C" void kernel_launch(void* const* d_in, const int* in_sizes, int n_in,
                              void* d_out, int out_size) {
    const float* xs  = (const float*)d_in[0];
    const float* W1x = (const float*)d_in[1];
    const float* W1h = (const float*)d_in[2];
    const float* b1  = (const float*)d_in[3];
    const float* W2  = (const float*)d_in[4];
    const float* b2  = (const float*)d_in[5];
    float* out = (float*)d_out;

    (void)in_sizes; (void)n_in; (void)out_size;

    cudaFuncSetAttribute(rnn_kernel, cudaFuncAttributeMaxDynamicSharedMemorySize,
                         SMEM_FLOATS * (int)sizeof(float));

    rnn_kernel<<<NCTA, THREADS, SMEM_FLOATS * sizeof(float)>>>(
        xs, W1x, W1h, b1, W2, b2, out);
}

// round 17
// speedup vs baseline: 1.6366x; 1.4504x over previous
#include <cuda_runtime.h>
#include <cstdint>

// Problem dims (fixed by the reference)
#define T_STEPS 512
#define BATCH   256
#define DIN     128
#define DH      512
#define DOUT    128

// Persistent mega-kernel: 8 row-blocks x 16 col-blocks of 32x32 tiles
#define NCTA     128
#define THREADS  256

// SMEM strides (floats)
#define W_STRIDE   672    // 640 k + skew headroom; 672 % 32 == 0
#define H_STRIDE   544    // 512 k + skew headroom; 544 % 32 == 0
#define XS_STRIDE  160    // 128 k + skew headroom
#define RED_STRIDE 1056   // 1024 outputs + skew headroom
#define SMEM_FLOATS (32 * W_STRIDE + 32 * H_STRIDE + 32 * XS_STRIDE + 8 * RED_STRIDE)

typedef unsigned long long ull;

// -------------------- device scratch (no allocation allowed) --------------------
__device__ float    g_h[2][BATCH * DH];            // ping-pong hidden state (zero; restored per run)
__device__ unsigned g_flag8[T_STEPS * NCTA * 8];   // per-(step,tile,producer-warp) flags (restored)
__device__ unsigned g_arr, g_go, g_fin;            // self-resetting grid barrier

// -------------------- asm helpers --------------------
__device__ __forceinline__ ull fma2(ull a, ull b, ull c) {
    ull d;
    asm("fma.rn.f32x2 %0, %1, %2, %3;" : "=l"(d) : "l"(a), "l"(b), "l"(c));
    return d;
}
__device__ __forceinline__ float sum2(ull v) {
    float lo, hi;
    asm("mov.b64 {%0, %1}, %2;" : "=f"(lo), "=f"(hi) : "l"(v));
    return lo + hi;
}
__device__ __forceinline__ unsigned ld_acquire(const unsigned* p) {
    unsigned v;
    asm volatile("ld.acquire.gpu.global.u32 %0, [%1];" : "=r"(v) : "l"(p) : "memory");
    return v;
}
__device__ __forceinline__ void st_release(unsigned* p, unsigned v) {
    asm volatile("st.release.gpu.global.u32 [%0], %1;" :: "l"(p), "r"(v) : "memory");
}
__device__ __forceinline__ void poll1(const unsigned* f) {
    while (ld_acquire(f) == 0u) { }
}

// ==================== single fused persistent kernel ====================
// Phase 1: 512 recurrence steps; xproj fused as k 512..639 of the weight block.
//   256 threads: (rg,cg,kg) = rows 8rg..+7, cols 4cg..+3, kg = warp (8-way split-k).
//   R13 mainloop placement (poll+LDG between gemm halves). R17 delta: per-WARP
//   release/acquire flags (dependency factorizes by warp: producer warp w writes
//   rows 4w..4w+3; consumer warp w restages exactly those rows) -> final step
//   barrier removed, releases decoupled from the CTA's slowest warp.
// Phase 2: self-resetting grid barrier.
// Phase 3: out = h_final @ W2 + b2 + state restore for the next graph replay.
__global__ void __launch_bounds__(THREADS, 1)
rnn_kernel(const float* __restrict__ xs, const float* __restrict__ W1x,
           const float* __restrict__ W1h, const float* __restrict__ b1p,
           const float* __restrict__ W2, const float* __restrict__ b2p,
           float* __restrict__ out) {
    extern __shared__ float sm[];
    float* w_smT  = sm;                                       // [32 cols][672], k 0..639
    float* h_sm   = sm + 32 * W_STRIDE;                       // [32 rows][544]
    float* xs_sm  = sm + 32 * W_STRIDE + 32 * H_STRIDE;       // [32 rows][160]
    float* red    = xs_sm + 32 * XS_STRIDE;                   // [8][1056] reduction buffer

    const int tid  = threadIdx.x;
    const int bid  = blockIdx.x;
    const int cb   = bid & 15;
    const int rb   = bid >> 4;
    const int col0 = cb * 32;
    const int row0 = rb * 32;

    const int w  = tid >> 5;          // warp (staging role + producer-warp id)
    const int l  = tid & 31;          // lane
    const int rg = tid & 3;           // GEMM row-group: rows 8rg..8rg+7
    const int cg = (tid >> 2) & 7;    // GEMM col-group: cols 4cg..4cg+3
    const int kg = w;                 // k-group: k offset kg*16 within each 128-chunk

    // ---- Prologue: stage W1h^T (k 0..511). Element (c,k) -> c*672 + 4*(c>>2) + k.
#pragma unroll
    for (int i = 0; i < 16; i++) {
        int idx = i * THREADS + tid;                          // 0..4095
        int c4  = idx & 7;
        int k   = idx >> 3;
        float4 v = *reinterpret_cast<const float4*>(W1h + (size_t)k * DH + col0 + c4 * 4);
        float* bp = w_smT + 4 * c4 + k;                       // skew = 4*c4 for all 4 elems
        bp[(4 * c4 + 0) * W_STRIDE] = v.x;
        bp[(4 * c4 + 1) * W_STRIDE] = v.y;
        bp[(4 * c4 + 2) * W_STRIDE] = v.z;
        bp[(4 * c4 + 3) * W_STRIDE] = v.w;
    }
    // ---- Prologue: stage W1x^T (k 512..639)
#pragma unroll
    for (int i = 0; i < 4; i++) {
        int idx = i * THREADS + tid;                          // 0..1023
        int c4  = idx & 7;
        int k   = idx >> 3;                                   // 0..127
        float4 v = *reinterpret_cast<const float4*>(W1x + (size_t)k * DH + col0 + c4 * 4);
        float* bp = w_smT + 4 * c4 + 512 + k;
        bp[(4 * c4 + 0) * W_STRIDE] = v.x;
        bp[(4 * c4 + 1) * W_STRIDE] = v.y;
        bp[(4 * c4 + 2) * W_STRIDE] = v.z;
        bp[(4 * c4 + 3) * W_STRIDE] = v.w;
    }
    // ---- Prologue: stage xs[0]
#pragma unroll
    for (int j = 0; j < 4; j++) {
        int r = 4 * w + j;
        float4 v = __ldg(reinterpret_cast<const float4*>(
            xs + (size_t)(row0 + r) * DIN + 4 * l));
        *reinterpret_cast<float4*>(
            xs_sm + (size_t)r * XS_STRIDE + 4 * (r >> 3) + 4 * l) = v;
    }
    const float bias = b1p[0];
    __syncthreads();

    // GEMM base pointers (skews folded in)
    const float* wc0 = w_smT + (size_t)(4 * cg + 0) * W_STRIDE + 4 * cg;
    const float* wc1 = wc0 + W_STRIDE;
    const float* wc2 = wc1 + W_STRIDE;
    const float* wc3 = wc2 + W_STRIDE;
    const float* hb  = h_sm  + (size_t)(8 * rg) * H_STRIDE  + 4 * rg;
    const float* xb  = xs_sm + (size_t)(8 * rg) * XS_STRIDE + 4 * rg;

    const float* hin  = g_h[0];
    float*       hout = g_h[1];
    const int    base = cb >> 2;                // rotated chunk start (spread L2 load)

    // =================== Phase 1: recurrence ===================
    for (int s = 0; s < T_STEPS; s++) {
        ull acc[8][4];
#pragma unroll
        for (int j = 0; j < 8; j++)
#pragma unroll
            for (int i = 0; i < 4; i++) acc[j][i] = 0ull;

        // 8-k GEMM slice: 8 rows x 4 cols, packed f32x2.
        auto gemm8 = [&](const float* hrow, int hstride, int hk, int wk) {
#pragma unroll
            for (int kk = 0; kk < 8; kk += 4) {
                ulonglong2 wv0 = *reinterpret_cast<const ulonglong2*>(wc0 + wk + kk);
                ulonglong2 wv1 = *reinterpret_cast<const ulonglong2*>(wc1 + wk + kk);
                ulonglong2 wv2 = *reinterpret_cast<const ulonglong2*>(wc2 + wk + kk);
                ulonglong2 wv3 = *reinterpret_cast<const ulonglong2*>(wc3 + wk + kk);
#pragma unroll
                for (int j = 0; j < 8; j++) {
                    ulonglong2 hv = *reinterpret_cast<const ulonglong2*>(
                        hrow + (size_t)j * hstride + hk + kk);
                    acc[j][0] = fma2(hv.x, wv0.x, acc[j][0]);
                    acc[j][0] = fma2(hv.y, wv0.y, acc[j][0]);
                    acc[j][1] = fma2(hv.x, wv1.x, acc[j][1]);
                    acc[j][1] = fma2(hv.y, wv1.y, acc[j][1]);
                    acc[j][2] = fma2(hv.x, wv2.x, acc[j][2]);
                    acc[j][2] = fma2(hv.y, wv2.y, acc[j][2]);
                    acc[j][3] = fma2(hv.x, wv3.x, acc[j][3]);
                    acc[j][3] = fma2(hv.y, wv3.y, acc[j][3]);
                }
            }
        };

        // Per-warp flag base: lane l restages rows 4w..4w+3 of tile (cn*4 + l>>3),
        // whose producer warp is w (orow>>2). Index: [(s-1, tile)*8 + w].
        const unsigned* fl =
            &g_flag8[(((size_t)(s - 1) * NCTA + rb * 16 + (l >> 3)) << 3) + w];
        const int ko = kg * 16;
        float4 t[4];

        // ---- xs half 1; acquire chunk c0's producer warp; LDG c0 under xs half 2 ----
        const int c0 = base;
        gemm8(xb, XS_STRIDE, ko, 512 + ko);
        if (s > 0) poll1(fl + c0 * 32);                       // acquire orders LDGs below
        {
            const float* src = hin + (size_t)(row0 + 4 * w) * DH + c0 * 128 + 4 * l;
#pragma unroll
            for (int j = 0; j < 4; j++)
                t[j] = __ldcg(reinterpret_cast<const float4*>(src + (size_t)j * DH));
        }
        gemm8(xb, XS_STRIDE, ko + 8, 520 + ko);
        {
#pragma unroll
            for (int j = 0; j < 4; j++) {
                int r = 4 * w + j;
                *reinterpret_cast<float4*>(
                    h_sm + (size_t)r * H_STRIDE + 4 * (r >> 3) + c0 * 128 + 4 * l) = t[j];
            }
        }
        __syncthreads();

        // ---- h chunks (R13 placement: poll+LDG between the two gemm halves) ----
#pragma unroll
        for (int j3 = 0; j3 < 3; j3++) {
            const int cj = (base + j3) & 3;
            const int cn = (base + j3 + 1) & 3;
            gemm8(hb, H_STRIDE, cj * 128 + ko, cj * 128 + ko);
            if (s > 0) poll1(fl + cn * 32);
            {
                const float* src = hin + (size_t)(row0 + 4 * w) * DH + cn * 128 + 4 * l;
#pragma unroll
                for (int j = 0; j < 4; j++)
                    t[j] = __ldcg(reinterpret_cast<const float4*>(src + (size_t)j * DH));
            }
            gemm8(hb, H_STRIDE, cj * 128 + ko + 8, cj * 128 + ko + 8);
            {
#pragma unroll
                for (int j = 0; j < 4; j++) {
                    int r = 4 * w + j;
                    *reinterpret_cast<float4*>(
                        h_sm + (size_t)r * H_STRIDE + 4 * (r >> 3) + cn * 128 + 4 * l) = t[j];
                }
            }
            __syncthreads();
        }

        // ---- last chunk; xs[s+1] LDG hidden under its second half ----
        {
            const int c3 = (base + 3) & 3;
            gemm8(hb, H_STRIDE, c3 * 128 + ko, c3 * 128 + ko);
            if (s < T_STEPS - 1) {
                const float* src = xs + ((size_t)(s + 1) * BATCH + row0 + 4 * w) * DIN + 4 * l;
#pragma unroll
                for (int j = 0; j < 4; j++)
                    t[j] = __ldg(reinterpret_cast<const float4*>(src + (size_t)j * DIN));
            }
            gemm8(hb, H_STRIDE, c3 * 128 + ko + 8, c3 * 128 + ko + 8);
            if (s < T_STEPS - 1) {
                // Safe: all warps' xs GEMM for step s finished before the c0 barrier.
#pragma unroll
                for (int j = 0; j < 4; j++) {
                    int r = 4 * w + j;
                    *reinterpret_cast<float4*>(
                        xs_sm + (size_t)r * XS_STRIDE + 4 * (r >> 3) + 4 * l) = t[j];
                }
            }
        }

        // ---- cross-kg reduction (skewed, conflict-free) ----
        {
            float* rbse = red + (size_t)kg * RED_STRIDE + 8 * rg + 4 * cg;
#pragma unroll
            for (int j = 0; j < 8; j++) {
                float4 pv;
                pv.x = sum2(acc[j][0]); pv.y = sum2(acc[j][1]);
                pv.z = sum2(acc[j][2]); pv.w = sum2(acc[j][3]);
                *reinterpret_cast<float4*>(rbse + (size_t)(8 * rg + j) * 32) = pv;
            }
        }
        __syncthreads();
        {
            const int orow = tid >> 3;                        // warp w -> rows 4w..4w+3
            const int ocol = 4 * (tid & 7);
            const float* rsrc = red + (size_t)orow * 32 + 8 * (orow >> 3) + ocol;
            float4 a = *reinterpret_cast<const float4*>(rsrc);
#pragma unroll
            for (int g = 1; g < 8; g++) {
                float4 b = *reinterpret_cast<const float4*>(rsrc + (size_t)g * RED_STRIDE);
                a.x += b.x; a.y += b.y; a.z += b.z; a.w += b.w;
            }
            float4 o;
            o.x = tanhf(a.x + bias); o.y = tanhf(a.y + bias);
            o.z = tanhf(a.z + bias); o.w = tanhf(a.w + bias);
            *reinterpret_cast<float4*>(
                hout + (size_t)(row0 + orow) * DH + col0 + ocol) = o;
        }
        // Per-warp early release: no final CTA barrier. __syncwarp orders all 32
        // lanes' STGs before lane 0's release (same idiom as CTA-level, warp-scoped).
        if (s < T_STEPS - 1) {
            __syncwarp();
            if (l == 0)
                st_release(&g_flag8[(((size_t)s * NCTA + bid) << 3) + w], 1u);
        }
        // red/xs_sm reuse WAR for step s+1 is ordered by step s+1's chunk barriers.

        const float* tmp = hin; hin = hout; hout = const_cast<float*>(tmp);
    }
    // 512 steps (even): final h lives in g_h[0].

    // =================== Phase 2: grid barrier (self-resetting) ===================
    __threadfence();
    __syncthreads();
    if (tid == 0) {
        unsigned my = atomicAdd(&g_arr, 1u);
        if (my == NCTA - 1) {
            g_arr = 0u;
            st_release(&g_go, 1u);
        } else {
            while (ld_acquire(&g_go) == 0u) { }
        }
        unsigned f2 = atomicAdd(&g_fin, 1u);
        if (f2 == NCTA - 1) {                                 // provably last past the poll
            g_fin = 0u;
            st_release(&g_go, 0u);
        }
    }
    __syncthreads();

    // =================== Phase 3: out = h_final @ W2 + b2, + state restore ===================
    float* hsm = sm;                                          // reuse SMEM
    const int r0 = 2 * bid;                                   // 2 batch rows per CTA
    {
        int r = tid >> 7, c4 = tid & 127;                     // 256 float4 = 2 rows
        float4 v = __ldcg(reinterpret_cast<const float4*>(
            &g_h[0][(size_t)(r0 + r) * DH + c4 * 4]));
        *reinterpret_cast<float4*>(&hsm[r * DH + c4 * 4]) = v;
    }
    __syncthreads();

    // Restore state for next replay: zero our flag slice (512 steps x 8 warps) + 2 h rows.
    {
        uint4 z4 = make_uint4(0u, 0u, 0u, 0u);
#pragma unroll
        for (int i = 0; i < 2; i++) {
            int s2 = i * 256 + tid;                           // 0..511
            uint4* p = reinterpret_cast<uint4*>(
                &g_flag8[((size_t)s2 * NCTA + bid) << 3]);
            p[0] = z4; p[1] = z4;
        }
        int r = tid >> 7, c4 = tid & 127;
        *reinterpret_cast<float4*>(&g_h[0][(size_t)(r0 + r) * DH + c4 * 4]) =
            make_float4(0.f, 0.f, 0.f, 0.f);
    }

    const float b2v = b2p[0];
    const int   orw = tid >> 7;                               // 0..1
    const int   o   = tid & 127;
    const float* hsr = hsm + orw * DH;
    float acc = b2v;
#pragma unroll 8
    for (int k = 0; k < DH; k++)
        acc += hsr[k] * __ldg(W2 + (size_t)k * DOUT + o);
    out[(size_t)(r0 + orw) * DOUT + o] = acc;
}

// -------------------- launch --------------------
extern "C" void kernel_launch(void* const* d_in, const int* in_sizes, int n_in,
                              void* d_out, int out_size) {
    const float* xs  = (const float*)d_in[0];
    const float* W1x = (const float*)d_in[1];
    const float* W1h = (const float*)d_in[2];
    const float* b1  = (const float*)d_in[3];
    const float* W2  = (const float*)d_in[4];
    const float* b2  = (const float*)d_in[5];
    float* out = (float*)d_out;

    (void)in_sizes; (void)n_in; (void)out_size;

    cudaFuncSetAttribute(rnn_kernel, cudaFuncAttributeMaxDynamicSharedMemorySize,
                         SMEM_FLOATS * (int)sizeof(float));

    rnn_kernel<<<NCTA, THREADS, SMEM_FLOATS * sizeof(float)>>>(
        xs, W1x, W1h, b1, W2, b2, out);
}